// round 10
// baseline (speedup 1.0000x reference)
#include <cuda_runtime.h>
#include <cstdint>

#define NMAX 50000
#define EMAX 400000
#define HEADS 4
#define DIM 64
#define HD 256   // HEADS*DIM

#define BM 256
#define BMp 260         // padded row length of transposed As (k-major)
#define BNp 68          // padded row length of Bs
#define GEMM_SMEM ((64 * BMp + 64 * BNp) * 4)   // 83,968 bytes

// ---------------- scratch (device globals; no allocation) ----------------
__device__ float g_xh    [(size_t)NMAX * HD];
__device__ float g_agg   [(size_t)NMAX * HD];
__device__ float g_ssrc  [(size_t)NMAX * HEADS];
__device__ float g_sdst  [(size_t)NMAX * HEADS];
__device__ int   g_cnt   [NMAX];
__device__ int   g_off   [NMAX + 1];
__device__ int   g_cursor[NMAX];
__device__ int   g_esrc  [EMAX];
__device__ float g_ealpha[(size_t)EMAX * HEADS];

// ---------------- packed f32x2 helpers (sm_103a) ----------------
__device__ __forceinline__ void ffma2(unsigned long long& acc,
                                      unsigned long long a, unsigned long long b) {
    asm("fma.rn.f32x2 %0, %1, %2, %0;" : "+l"(acc) : "l"(a), "l"(b));
}
__device__ __forceinline__ unsigned long long pack2(float x) {
    unsigned long long r;
    asm("mov.b64 %0, {%1, %1};" : "=l"(r) : "r"(__float_as_uint(x)));
    return r;
}
__device__ __forceinline__ float2 unpack2(unsigned long long v) {
    float2 f;
    asm("mov.b64 {%0, %1}, %2;" : "=f"(f.x), "=f"(f.y) : "l"(v));
    return f;
}

// ---------------- zero histogram ----------------
__global__ void k_hzero(int* __restrict__ cnt, int n) {
    int i = blockIdx.x * blockDim.x + threadIdx.x;
    if (i < n) cnt[i] = 0;
}

// ---------------- histogram of dst ----------------
__global__ void k_hist(const int* __restrict__ ei, int* __restrict__ cnt, int E) {
    int e = blockIdx.x * blockDim.x + threadIdx.x;
    if (e < E) atomicAdd(&cnt[ei[e]], 1);
}

// ---------------- single-block exclusive scan ----------------
__global__ __launch_bounds__(1024) void k_scan(const int* __restrict__ cnt,
                                               int* __restrict__ off,
                                               int* __restrict__ cursor, int n)
{
    __shared__ int warpsum[32];
    const int tid  = threadIdx.x;
    const int lane = tid & 31;
    const int wid  = tid >> 5;
    int base = 0;
    for (int chunk = 0; chunk < n; chunk += 1024) {
        int idx = chunk + tid;
        int v = (idx < n) ? cnt[idx] : 0;
        int x = v;
        #pragma unroll
        for (int o = 1; o < 32; o <<= 1) {
            int y = __shfl_up_sync(0xffffffffu, x, o);
            if (lane >= o) x += y;
        }
        if (lane == 31) warpsum[wid] = x;
        __syncthreads();
        if (wid == 0) {
            int w = (lane < 32) ? warpsum[lane] : 0;
            #pragma unroll
            for (int o = 1; o < 32; o <<= 1) {
                int y = __shfl_up_sync(0xffffffffu, w, o);
                if (lane >= o) w += y;
            }
            warpsum[lane] = w;
        }
        __syncthreads();
        int excl = x - v + (wid > 0 ? warpsum[wid - 1] : 0) + base;
        if (idx < n) { off[idx] = excl; cursor[idx] = excl; }
        int total = warpsum[31];
        __syncthreads();
        base += total;
    }
    if (tid == 0) off[n] = base;
}

// ---------------- GEMM1: xh = x @ W_lin^T, fused scores. 256x64 tile, 8x8/thread ----------------
__global__ __launch_bounds__(256) void k_gemm1(
    const float* __restrict__ A,     // x [M,64]
    const float* __restrict__ B,     // W_lin [256,64]
    const float* __restrict__ asrc, const float* __restrict__ adst,
    float* __restrict__ C,           // xh [M,256]
    float* __restrict__ ssrc, float* __restrict__ sdst, int M)
{
    extern __shared__ float sm[];
    float* As = sm;                  // [64][BMp] k-major (transposed)
    float* Bs = sm + 64 * BMp;       // [64][BNp]
    const int t    = threadIdx.x;
    const int m0   = blockIdx.x * BM;
    const int h    = blockIdx.y;
    const int col0 = (t & 7) * 8;
    const int row0 = (t >> 3) * 8;
    const float* Bt = B + (size_t)h * 64 * DIM;
    unsigned long long acc[8][4] = {};

    // load A tile transposed: As[k][row]
    #pragma unroll
    for (int it = 0; it < 16; ++it) {
        int f4  = t + it * 256;
        int row = f4 >> 4;
        int k4  = (f4 & 15) * 4;
        float4 v = make_float4(0.f, 0.f, 0.f, 0.f);
        int gr = m0 + row;
        if (gr < M) v = *(const float4*)(A + (size_t)gr * DIM + k4);
        As[(k4 + 0) * BMp + row] = v.x;
        As[(k4 + 1) * BMp + row] = v.y;
        As[(k4 + 2) * BMp + row] = v.z;
        As[(k4 + 3) * BMp + row] = v.w;
    }
    // load B tile: Bs[k][c]
    #pragma unroll
    for (int it = 0; it < 4; ++it) {
        int lin = t + it * 256;
        int c   = lin >> 4;
        int k4  = (lin & 15) * 4;
        float4 v = *(const float4*)(Bt + (size_t)c * DIM + k4);
        Bs[(k4 + 0) * BNp + c] = v.x;
        Bs[(k4 + 1) * BNp + c] = v.y;
        Bs[(k4 + 2) * BNp + c] = v.z;
        Bs[(k4 + 3) * BNp + c] = v.w;
    }
    __syncthreads();

    #pragma unroll 4
    for (int k = 0; k < 64; ++k) {
        float4 a0 = *(const float4*)&As[k * BMp + row0];
        float4 a1 = *(const float4*)&As[k * BMp + row0 + 4];
        ulonglong2 b01 = *(const ulonglong2*)&Bs[k * BNp + col0];
        ulonglong2 b23 = *(const ulonglong2*)&Bs[k * BNp + col0 + 4];
        unsigned long long ap;
        ap = pack2(a0.x); ffma2(acc[0][0], ap, b01.x); ffma2(acc[0][1], ap, b01.y); ffma2(acc[0][2], ap, b23.x); ffma2(acc[0][3], ap, b23.y);
        ap = pack2(a0.y); ffma2(acc[1][0], ap, b01.x); ffma2(acc[1][1], ap, b01.y); ffma2(acc[1][2], ap, b23.x); ffma2(acc[1][3], ap, b23.y);
        ap = pack2(a0.z); ffma2(acc[2][0], ap, b01.x); ffma2(acc[2][1], ap, b01.y); ffma2(acc[2][2], ap, b23.x); ffma2(acc[2][3], ap, b23.y);
        ap = pack2(a0.w); ffma2(acc[3][0], ap, b01.x); ffma2(acc[3][1], ap, b01.y); ffma2(acc[3][2], ap, b23.x); ffma2(acc[3][3], ap, b23.y);
        ap = pack2(a1.x); ffma2(acc[4][0], ap, b01.x); ffma2(acc[4][1], ap, b01.y); ffma2(acc[4][2], ap, b23.x); ffma2(acc[4][3], ap, b23.y);
        ap = pack2(a1.y); ffma2(acc[5][0], ap, b01.x); ffma2(acc[5][1], ap, b01.y); ffma2(acc[5][2], ap, b23.x); ffma2(acc[5][3], ap, b23.y);
        ap = pack2(a1.z); ffma2(acc[6][0], ap, b01.x); ffma2(acc[6][1], ap, b01.y); ffma2(acc[6][2], ap, b23.x); ffma2(acc[6][3], ap, b23.y);
        ap = pack2(a1.w); ffma2(acc[7][0], ap, b01.x); ffma2(acc[7][1], ap, b01.y); ffma2(acc[7][2], ap, b23.x); ffma2(acc[7][3], ap, b23.y);
    }

    // epilogue: store xh + fused scores (row by row; shfl is warp-uniform)
    float4 va0 = __ldg((const float4*)(asrc + h * DIM + col0));
    float4 va1 = __ldg((const float4*)(asrc + h * DIM + col0 + 4));
    float4 vd0 = __ldg((const float4*)(adst + h * DIM + col0));
    float4 vd1 = __ldg((const float4*)(adst + h * DIM + col0 + 4));
    #pragma unroll
    for (int i = 0; i < 8; ++i) {
        float2 p0 = unpack2(acc[i][0]);
        float2 p1 = unpack2(acc[i][1]);
        float2 p2 = unpack2(acc[i][2]);
        float2 p3 = unpack2(acc[i][3]);
        int gr = m0 + row0 + i;
        if (gr < M) {
            *(float4*)(C + (size_t)gr * HD + h * 64 + col0)     = make_float4(p0.x, p0.y, p1.x, p1.y);
            *(float4*)(C + (size_t)gr * HD + h * 64 + col0 + 4) = make_float4(p2.x, p2.y, p3.x, p3.y);
        }
        float ss = p0.x * va0.x + p0.y * va0.y + p1.x * va0.z + p1.y * va0.w
                 + p2.x * va1.x + p2.y * va1.y + p3.x * va1.z + p3.y * va1.w;
        float sd = p0.x * vd0.x + p0.y * vd0.y + p1.x * vd0.z + p1.y * vd0.w
                 + p2.x * vd1.x + p2.y * vd1.y + p3.x * vd1.z + p3.y * vd1.w;
        #pragma unroll
        for (int o = 1; o < 8; o <<= 1) {
            ss += __shfl_xor_sync(0xffffffffu, ss, o);
            sd += __shfl_xor_sync(0xffffffffu, sd, o);
        }
        if ((t & 7) == 0 && gr < M) {
            ssrc[(size_t)gr * HEADS + h] = ss;
            sdst[(size_t)gr * HEADS + h] = sd;
        }
    }
}

// ---------------- scatter edges into dst-sorted order, alpha inline ----------------
__global__ void k_scatter(const int* __restrict__ ei,
                          const float* __restrict__ ssrc, const float* __restrict__ sdst,
                          int* __restrict__ cursor,
                          int* __restrict__ esrc, float* __restrict__ ealpha, int E)
{
    int e = blockIdx.x * blockDim.x + threadIdx.x;
    if (e >= E) return;
    int i = ei[e];        // dst
    int j = ei[E + e];    // src
    float4 sd = *(const float4*)(sdst + (size_t)i * 4);
    float4 ss = *(const float4*)(ssrc + (size_t)j * 4);
    float a0 = sd.x + ss.x; a0 = a0 > 0.f ? a0 : 0.2f * a0;
    float a1 = sd.y + ss.y; a1 = a1 > 0.f ? a1 : 0.2f * a1;
    float a2 = sd.z + ss.z; a2 = a2 > 0.f ? a2 : 0.2f * a2;
    float a3 = sd.w + ss.w; a3 = a3 > 0.f ? a3 : 0.2f * a3;
    int pos = atomicAdd(&cursor[i], 1);
    esrc[pos] = j;
    *(float4*)(ealpha + (size_t)pos * 4) =
        make_float4(expf(a0), expf(a1), expf(a2), expf(a3));
}

// ---------------- CSR aggregation: one warp per dst node ----------------
__global__ __launch_bounds__(256) void k_agg_csr(
    const int* __restrict__ off, const int* __restrict__ esrc,
    const float* __restrict__ ealpha, const float* __restrict__ xh,
    float* __restrict__ agg, int n)
{
    int w    = (blockIdx.x * blockDim.x + threadIdx.x) >> 5;
    int lane = threadIdx.x & 31;
    if (w >= n) return;
    int beg = off[w], end = off[w + 1];
    int head = lane >> 3;
    float acc0 = 0.f, acc1 = 0.f, acc2 = 0.f, acc3 = 0.f;
    float acc4 = 0.f, acc5 = 0.f, acc6 = 0.f, acc7 = 0.f;
    float dsum = 0.f;

    int e = beg;
    int j = 0; float a = 0.f;
    if (e < end) { j = esrc[e]; a = ealpha[(size_t)e * 4 + head]; }
    while (e < end) {
        int jn = 0; float an = 0.f;
        if (e + 1 < end) { jn = esrc[e + 1]; an = ealpha[(size_t)(e + 1) * 4 + head]; }
        const float* s = xh + (size_t)j * HD + lane * 8;
        float4 v0 = *(const float4*)(s);
        float4 v1 = *(const float4*)(s + 4);
        acc0 += a * v0.x; acc1 += a * v0.y; acc2 += a * v0.z; acc3 += a * v0.w;
        acc4 += a * v1.x; acc5 += a * v1.y; acc6 += a * v1.z; acc7 += a * v1.w;
        dsum += a;
        j = jn; a = an; ++e;
    }
    float inv = 1.0f / (dsum + 1e-9f);
    float* d = agg + (size_t)w * HD + lane * 8;
    *(float4*)(d)     = make_float4(acc0 * inv, acc1 * inv, acc2 * inv, acc3 * inv);
    *(float4*)(d + 4) = make_float4(acc4 * inv, acc5 * inv, acc6 * inv, acc7 * inv);
}

// ---------------- GEMM2: out = LN(ELU(agg @ W_out^T + b) + x). 256x64 tile, 8x8 ----------------
__global__ __launch_bounds__(256) void k_gemm2(
    const float* __restrict__ A,     // agg [M,256]
    const float* __restrict__ B,     // W_out [64,256]
    const float* __restrict__ x,
    const float* __restrict__ bias,
    const float* __restrict__ lng, const float* __restrict__ lnb,
    float* __restrict__ out, int M)
{
    extern __shared__ float sm[];
    float* As = sm;
    float* Bs = sm + 64 * BMp;
    const int t    = threadIdx.x;
    const int m0   = blockIdx.x * BM;
    const int col0 = (t & 7) * 8;
    const int row0 = (t >> 3) * 8;
    unsigned long long acc[8][4] = {};

    for (int kc = 0; kc < HD; kc += 64) {
        #pragma unroll
        for (int it = 0; it < 16; ++it) {
            int f4  = t + it * 256;
            int row = f4 >> 4;
            int k4  = (f4 & 15) * 4;
            float4 v = make_float4(0.f, 0.f, 0.f, 0.f);
            int gr = m0 + row;
            if (gr < M) v = *(const float4*)(A + (size_t)gr * HD + kc + k4);
            As[(k4 + 0) * BMp + row] = v.x;
            As[(k4 + 1) * BMp + row] = v.y;
            As[(k4 + 2) * BMp + row] = v.z;
            As[(k4 + 3) * BMp + row] = v.w;
        }
        #pragma unroll
        for (int it = 0; it < 4; ++it) {
            int lin = t + it * 256;
            int c   = lin >> 4;
            int k4  = (lin & 15) * 4;
            float4 v = *(const float4*)(B + (size_t)c * HD + kc + k4);
            Bs[(k4 + 0) * BNp + c] = v.x;
            Bs[(k4 + 1) * BNp + c] = v.y;
            Bs[(k4 + 2) * BNp + c] = v.z;
            Bs[(k4 + 3) * BNp + c] = v.w;
        }
        __syncthreads();
        #pragma unroll 4
        for (int k = 0; k < 64; ++k) {
            float4 a0 = *(const float4*)&As[k * BMp + row0];
            float4 a1 = *(const float4*)&As[k * BMp + row0 + 4];
            ulonglong2 b01 = *(const ulonglong2*)&Bs[k * BNp + col0];
            ulonglong2 b23 = *(const ulonglong2*)&Bs[k * BNp + col0 + 4];
            unsigned long long ap;
            ap = pack2(a0.x); ffma2(acc[0][0], ap, b01.x); ffma2(acc[0][1], ap, b01.y); ffma2(acc[0][2], ap, b23.x); ffma2(acc[0][3], ap, b23.y);
            ap = pack2(a0.y); ffma2(acc[1][0], ap, b01.x); ffma2(acc[1][1], ap, b01.y); ffma2(acc[1][2], ap, b23.x); ffma2(acc[1][3], ap, b23.y);
            ap = pack2(a0.z); ffma2(acc[2][0], ap, b01.x); ffma2(acc[2][1], ap, b01.y); ffma2(acc[2][2], ap, b23.x); ffma2(acc[2][3], ap, b23.y);
            ap = pack2(a0.w); ffma2(acc[3][0], ap, b01.x); ffma2(acc[3][1], ap, b01.y); ffma2(acc[3][2], ap, b23.x); ffma2(acc[3][3], ap, b23.y);
            ap = pack2(a1.x); ffma2(acc[4][0], ap, b01.x); ffma2(acc[4][1], ap, b01.y); ffma2(acc[4][2], ap, b23.x); ffma2(acc[4][3], ap, b23.y);
            ap = pack2(a1.y); ffma2(acc[5][0], ap, b01.x); ffma2(acc[5][1], ap, b01.y); ffma2(acc[5][2], ap, b23.x); ffma2(acc[5][3], ap, b23.y);
            ap = pack2(a1.z); ffma2(acc[6][0], ap, b01.x); ffma2(acc[6][1], ap, b01.y); ffma2(acc[6][2], ap, b23.x); ffma2(acc[6][3], ap, b23.y);
            ap = pack2(a1.w); ffma2(acc[7][0], ap, b01.x); ffma2(acc[7][1], ap, b01.y); ffma2(acc[7][2], ap, b23.x); ffma2(acc[7][3], ap, b23.y);
        }
        __syncthreads();
    }

    // epilogue: bias + ELU + residual + LayerNorm, row by row
    float4 bb0 = __ldg((const float4*)(bias + col0));
    float4 bb1 = __ldg((const float4*)(bias + col0 + 4));
    float4 gg0 = __ldg((const float4*)(lng + col0));
    float4 gg1 = __ldg((const float4*)(lng + col0 + 4));
    float4 lb0 = __ldg((const float4*)(lnb + col0));
    float4 lb1 = __ldg((const float4*)(lnb + col0 + 4));
    #pragma unroll
    for (int i = 0; i < 8; ++i) {
        float2 p0 = unpack2(acc[i][0]);
        float2 p1 = unpack2(acc[i][1]);
        float2 p2 = unpack2(acc[i][2]);
        float2 p3 = unpack2(acc[i][3]);
        float y[8] = {p0.x + bb0.x, p0.y + bb0.y, p1.x + bb0.z, p1.y + bb0.w,
                      p2.x + bb1.x, p2.y + bb1.y, p3.x + bb1.z, p3.y + bb1.w};
        int gr = m0 + row0 + i;
        float4 xr0 = make_float4(0.f, 0.f, 0.f, 0.f);
        float4 xr1 = make_float4(0.f, 0.f, 0.f, 0.f);
        if (gr < M) {
            xr0 = *(const float4*)(x + (size_t)gr * DIM + col0);
            xr1 = *(const float4*)(x + (size_t)gr * DIM + col0 + 4);
        }
        float xa[8] = {xr0.x, xr0.y, xr0.z, xr0.w, xr1.x, xr1.y, xr1.z, xr1.w};
        float s = 0.f, q = 0.f;
        #pragma unroll
        for (int c = 0; c < 8; ++c) {
            float v = y[c];
            v = v > 0.f ? v : (expf(v) - 1.0f);
            float yy = v + xa[c];
            y[c] = yy;
            s += yy; q += yy * yy;
        }
        #pragma unroll
        for (int o = 1; o < 8; o <<= 1) {
            s += __shfl_xor_sync(0xffffffffu, s, o);
            q += __shfl_xor_sync(0xffffffffu, q, o);
        }
        if (gr < M) {
            float mu  = s * (1.0f / 64.0f);
            float var = q * (1.0f / 64.0f) - mu * mu;
            float inv = rsqrtf(var + 1e-5f);
            float4 o0, o1;
            o0.x = (y[0] - mu) * inv * gg0.x + lb0.x;
            o0.y = (y[1] - mu) * inv * gg0.y + lb0.y;
            o0.z = (y[2] - mu) * inv * gg0.z + lb0.z;
            o0.w = (y[3] - mu) * inv * gg0.w + lb0.w;
            o1.x = (y[4] - mu) * inv * gg1.x + lb1.x;
            o1.y = (y[5] - mu) * inv * gg1.y + lb1.y;
            o1.z = (y[6] - mu) * inv * gg1.z + lb1.z;
            o1.w = (y[7] - mu) * inv * gg1.w + lb1.w;
            *(float4*)(out + (size_t)gr * DIM + col0)     = o0;
            *(float4*)(out + (size_t)gr * DIM + col0 + 4) = o1;
        }
    }
}

// ---------------- launch ----------------
extern "C" void kernel_launch(void* const* d_in, const int* in_sizes, int n_in,
                              void* d_out, int out_size)
{
    const float* x    = (const float*)d_in[0];
    const int*   ei   = (const int*)d_in[1];   // int32 [2,E]
    const float* Wlin = (const float*)d_in[2];
    const float* asrc = (const float*)d_in[3];
    const float* adst = (const float*)d_in[4];
    const float* Wout = (const float*)d_in[5];
    const float* bout = (const float*)d_in[6];
    const float* lng  = (const float*)d_in[7];
    const float* lnb  = (const float*)d_in[8];
    float*       out  = (float*)d_out;

    int n = in_sizes[0] / DIM;
    int E = in_sizes[1] / 2;
    if (n > NMAX) n = NMAX;
    if (E > EMAX) E = EMAX;

    float *p_xh, *p_agg, *p_ssrc, *p_sdst, *p_ealpha;
    int *p_cnt, *p_off, *p_cursor, *p_esrc;
    cudaGetSymbolAddress((void**)&p_xh,     g_xh);
    cudaGetSymbolAddress((void**)&p_agg,    g_agg);
    cudaGetSymbolAddress((void**)&p_ssrc,   g_ssrc);
    cudaGetSymbolAddress((void**)&p_sdst,   g_sdst);
    cudaGetSymbolAddress((void**)&p_cnt,    g_cnt);
    cudaGetSymbolAddress((void**)&p_off,    g_off);
    cudaGetSymbolAddress((void**)&p_cursor, g_cursor);
    cudaGetSymbolAddress((void**)&p_esrc,   g_esrc);
    cudaGetSymbolAddress((void**)&p_ealpha, g_ealpha);

    cudaFuncSetAttribute(k_gemm1, cudaFuncAttributeMaxDynamicSharedMemorySize, GEMM_SMEM);
    cudaFuncSetAttribute(k_gemm2, cudaFuncAttributeMaxDynamicSharedMemorySize, GEMM_SMEM);

    // 1) dst-degree histogram
    k_hzero<<<(n + 255) / 256, 256>>>(p_cnt, n);
    k_hist <<<(E + 255) / 256, 256>>>(ei, p_cnt, E);

    // 2) CSR offsets
    k_scan<<<1, 1024>>>(p_cnt, p_off, p_cursor, n);

    // 3) xh = x @ W_lin^T with fused scores
    dim3 g1((n + BM - 1) / BM, HEADS);
    k_gemm1<<<g1, 256, GEMM_SMEM>>>(x, Wlin, asrc, adst, p_xh, p_ssrc, p_sdst, n);

    // 4) scatter edges (dst-sorted) with inline alpha
    k_scatter<<<(E + 255) / 256, 256>>>(ei, p_ssrc, p_sdst, p_cursor, p_esrc, p_ealpha, E);

    // 5) pull aggregation
    k_agg_csr<<<(n * 32 + 255) / 256, 256>>>(p_off, p_esrc, p_ealpha, p_xh, p_agg, n);

    // 6) out = LN(ELU(agg @ W_out^T + b) + x)
    k_gemm2<<<(n + BM - 1) / BM, 256, GEMM_SMEM>>>(p_agg, Wout, x, bout, lng, lnb, out, n);
}

// round 11
// speedup vs baseline: 1.3092x; 1.3092x over previous
#include <cuda_runtime.h>
#include <cstdint>

#define NMAX 50000
#define EMAX 400000
#define HEADS 4
#define DIM 64
#define HD 256   // HEADS*DIM

#define PAD 68                       // padded row length (floats)
#define AS_FLOATS (128 * PAD)
#define BS_FLOATS (64 * PAD)
#define GEMM_SMEM_B ((AS_FLOATS + BS_FLOATS) * 4)   // 52,224 bytes

// ---------------- scratch (device globals; no allocation) ----------------
__device__ float g_xh    [(size_t)NMAX * HD];
__device__ float g_agg   [(size_t)NMAX * HD];
__device__ float g_ssrc  [(size_t)NMAX * HEADS];
__device__ float g_sdst  [(size_t)NMAX * HEADS];
__device__ int   g_cnt   [NMAX];
__device__ int   g_off   [NMAX + 1];
__device__ int   g_cursor[NMAX];
__device__ int   g_esrc  [EMAX];
__device__ float g_ealpha[(size_t)EMAX * HEADS];

// ---------------- tf32 mma helpers ----------------
__device__ __forceinline__ uint32_t f2tf32(float x) {
    uint32_t r;
    asm("cvt.rna.tf32.f32 %0, %1;" : "=r"(r) : "f"(x));
    return r;
}
__device__ __forceinline__ void hilo(float v, uint32_t& hi, uint32_t& lo) {
    hi = f2tf32(v);
    lo = f2tf32(v - __uint_as_float(hi));
}
__device__ __forceinline__ void mma_tf32(float& d0, float& d1, float& d2, float& d3,
                                         uint32_t a0, uint32_t a1, uint32_t a2, uint32_t a3,
                                         uint32_t b0, uint32_t b1) {
    asm("mma.sync.aligned.m16n8k8.row.col.f32.tf32.tf32.f32 "
        "{%0,%1,%2,%3}, {%4,%5,%6,%7}, {%8,%9}, {%0,%1,%2,%3};"
        : "+f"(d0), "+f"(d1), "+f"(d2), "+f"(d3)
        : "r"(a0), "r"(a1), "r"(a2), "r"(a3), "r"(b0), "r"(b1));
}

// ---------------- zero histogram ----------------
__global__ void k_hzero(int* __restrict__ cnt, int n) {
    int i = blockIdx.x * blockDim.x + threadIdx.x;
    if (i < n) cnt[i] = 0;
}

// ---------------- histogram of dst ----------------
__global__ void k_hist(const int* __restrict__ ei, int* __restrict__ cnt, int E) {
    int e = blockIdx.x * blockDim.x + threadIdx.x;
    if (e < E) atomicAdd(&cnt[ei[e]], 1);
}

// ---------------- single-block exclusive scan ----------------
__global__ __launch_bounds__(1024) void k_scan(const int* __restrict__ cnt,
                                               int* __restrict__ off,
                                               int* __restrict__ cursor, int n)
{
    __shared__ int warpsum[32];
    const int tid  = threadIdx.x;
    const int lane = tid & 31;
    const int wid  = tid >> 5;
    int base = 0;
    for (int chunk = 0; chunk < n; chunk += 1024) {
        int idx = chunk + tid;
        int v = (idx < n) ? cnt[idx] : 0;
        int x = v;
        #pragma unroll
        for (int o = 1; o < 32; o <<= 1) {
            int y = __shfl_up_sync(0xffffffffu, x, o);
            if (lane >= o) x += y;
        }
        if (lane == 31) warpsum[wid] = x;
        __syncthreads();
        if (wid == 0) {
            int w = (lane < 32) ? warpsum[lane] : 0;
            #pragma unroll
            for (int o = 1; o < 32; o <<= 1) {
                int y = __shfl_up_sync(0xffffffffu, w, o);
                if (lane >= o) w += y;
            }
            warpsum[lane] = w;
        }
        __syncthreads();
        int excl = x - v + (wid > 0 ? warpsum[wid - 1] : 0) + base;
        if (idx < n) { off[idx] = excl; cursor[idx] = excl; }
        int total = warpsum[31];
        __syncthreads();
        base += total;
    }
    if (tid == 0) off[n] = base;
}

// ---------------- GEMM1 (tf32 mma): xh = x @ W_lin^T, fused scores ----------------
// Block: 128 rows x 64 cols (one head). 8 warps, each one m16 tile x full N=64.
__global__ __launch_bounds__(256) void k_gemm1(
    const float* __restrict__ A,     // x [M,64]
    const float* __restrict__ B,     // W_lin [256,64]
    const float* __restrict__ asrc, const float* __restrict__ adst,
    float* __restrict__ C,           // xh [M,256]
    float* __restrict__ ssrc, float* __restrict__ sdst, int M)
{
    extern __shared__ float sm[];
    float* As = sm;                  // [128][PAD]
    float* Bs = sm + AS_FLOATS;      // [64][PAD]  Bs[n][k] = W[h*64+n][k]
    const int t    = threadIdx.x;
    const int lane = t & 31;
    const int w    = t >> 5;
    const int gid  = lane >> 2;
    const int tid4 = lane & 3;
    const int m0   = blockIdx.x * 128;
    const int h    = blockIdx.y;
    const float* Bt = B + (size_t)h * 64 * DIM;

    // fill A tile [128][64]
    #pragma unroll
    for (int it = 0; it < 8; ++it) {
        int idx = t + it * 256;
        int row = idx >> 4;
        int k4  = (idx & 15) * 4;
        float4 v = make_float4(0.f, 0.f, 0.f, 0.f);
        int gr = m0 + row;
        if (gr < M) v = *(const float4*)(A + (size_t)gr * DIM + k4);
        *(float4*)&As[row * PAD + k4] = v;
    }
    // fill B tile [64][64]
    #pragma unroll
    for (int it = 0; it < 4; ++it) {
        int idx = t + it * 256;
        int nr  = idx >> 4;
        int k4  = (idx & 15) * 4;
        *(float4*)&Bs[nr * PAD + k4] = *(const float4*)(Bt + (size_t)nr * DIM + k4);
    }
    __syncthreads();

    float acc[8][4] = {};  // 8 n8-tiles x 4 regs
    const int r0 = w * 16 + gid;       // local row for c0/c1
    const int r1 = r0 + 8;             // local row for c2/c3

    #pragma unroll
    for (int ks = 0; ks < 8; ++ks) {
        int c0 = ks * 8 + tid4;
        int c1 = c0 + 4;
        uint32_t ah[4], al[4];
        hilo(As[r0 * PAD + c0], ah[0], al[0]);
        hilo(As[r1 * PAD + c0], ah[1], al[1]);
        hilo(As[r0 * PAD + c1], ah[2], al[2]);
        hilo(As[r1 * PAD + c1], ah[3], al[3]);
        #pragma unroll
        for (int nt = 0; nt < 8; ++nt) {
            uint32_t bh0, bl0, bh1, bl1;
            hilo(Bs[(nt * 8 + gid) * PAD + c0], bh0, bl0);
            hilo(Bs[(nt * 8 + gid) * PAD + c1], bh1, bl1);
            mma_tf32(acc[nt][0], acc[nt][1], acc[nt][2], acc[nt][3],
                     ah[0], ah[1], ah[2], ah[3], bh0, bh1);
            mma_tf32(acc[nt][0], acc[nt][1], acc[nt][2], acc[nt][3],
                     ah[0], ah[1], ah[2], ah[3], bl0, bl1);
            mma_tf32(acc[nt][0], acc[nt][1], acc[nt][2], acc[nt][3],
                     al[0], al[1], al[2], al[3], bh0, bh1);
        }
    }

    // epilogue: store xh + fused per-row scores
    int gr0 = m0 + r0;
    int gr1 = m0 + r1;
    float ss0 = 0.f, sd0 = 0.f, ss1 = 0.f, sd1 = 0.f;
    #pragma unroll
    for (int nt = 0; nt < 8; ++nt) {
        int col = nt * 8 + tid4 * 2;
        float2 av = __ldg((const float2*)(asrc + h * DIM + col));
        float2 dv = __ldg((const float2*)(adst + h * DIM + col));
        if (gr0 < M)
            *(float2*)(C + (size_t)gr0 * HD + h * 64 + col) = make_float2(acc[nt][0], acc[nt][1]);
        if (gr1 < M)
            *(float2*)(C + (size_t)gr1 * HD + h * 64 + col) = make_float2(acc[nt][2], acc[nt][3]);
        ss0 += acc[nt][0] * av.x + acc[nt][1] * av.y;
        sd0 += acc[nt][0] * dv.x + acc[nt][1] * dv.y;
        ss1 += acc[nt][2] * av.x + acc[nt][3] * av.y;
        sd1 += acc[nt][2] * dv.x + acc[nt][3] * dv.y;
    }
    #pragma unroll
    for (int o = 1; o < 4; o <<= 1) {
        ss0 += __shfl_xor_sync(0xffffffffu, ss0, o);
        sd0 += __shfl_xor_sync(0xffffffffu, sd0, o);
        ss1 += __shfl_xor_sync(0xffffffffu, ss1, o);
        sd1 += __shfl_xor_sync(0xffffffffu, sd1, o);
    }
    if (tid4 == 0) {
        if (gr0 < M) {
            ssrc[(size_t)gr0 * HEADS + h] = ss0;
            sdst[(size_t)gr0 * HEADS + h] = sd0;
        }
        if (gr1 < M) {
            ssrc[(size_t)gr1 * HEADS + h] = ss1;
            sdst[(size_t)gr1 * HEADS + h] = sd1;
        }
    }
}

// ---------------- scatter edges into dst-sorted order, alpha inline ----------------
__global__ void k_scatter(const int* __restrict__ ei,
                          const float* __restrict__ ssrc, const float* __restrict__ sdst,
                          int* __restrict__ cursor,
                          int* __restrict__ esrc, float* __restrict__ ealpha, int E)
{
    int e = blockIdx.x * blockDim.x + threadIdx.x;
    if (e >= E) return;
    int i = ei[e];        // dst
    int j = ei[E + e];    // src
    float4 sd = *(const float4*)(sdst + (size_t)i * 4);
    float4 ss = *(const float4*)(ssrc + (size_t)j * 4);
    float a0 = sd.x + ss.x; a0 = a0 > 0.f ? a0 : 0.2f * a0;
    float a1 = sd.y + ss.y; a1 = a1 > 0.f ? a1 : 0.2f * a1;
    float a2 = sd.z + ss.z; a2 = a2 > 0.f ? a2 : 0.2f * a2;
    float a3 = sd.w + ss.w; a3 = a3 > 0.f ? a3 : 0.2f * a3;
    int pos = atomicAdd(&cursor[i], 1);
    esrc[pos] = j;
    *(float4*)(ealpha + (size_t)pos * 4) =
        make_float4(expf(a0), expf(a1), expf(a2), expf(a3));
}

// ---------------- CSR aggregation: one warp per dst node ----------------
__global__ __launch_bounds__(256) void k_agg_csr(
    const int* __restrict__ off, const int* __restrict__ esrc,
    const float* __restrict__ ealpha, const float* __restrict__ xh,
    float* __restrict__ agg, int n)
{
    int w    = (blockIdx.x * blockDim.x + threadIdx.x) >> 5;
    int lane = threadIdx.x & 31;
    if (w >= n) return;
    int beg = off[w], end = off[w + 1];
    int head = lane >> 3;
    float acc0 = 0.f, acc1 = 0.f, acc2 = 0.f, acc3 = 0.f;
    float acc4 = 0.f, acc5 = 0.f, acc6 = 0.f, acc7 = 0.f;
    float dsum = 0.f;

    int e = beg;
    int j = 0; float a = 0.f;
    if (e < end) { j = esrc[e]; a = ealpha[(size_t)e * 4 + head]; }
    while (e < end) {
        int jn = 0; float an = 0.f;
        if (e + 1 < end) { jn = esrc[e + 1]; an = ealpha[(size_t)(e + 1) * 4 + head]; }
        const float* s = xh + (size_t)j * HD + lane * 8;
        float4 v0 = *(const float4*)(s);
        float4 v1 = *(const float4*)(s + 4);
        acc0 += a * v0.x; acc1 += a * v0.y; acc2 += a * v0.z; acc3 += a * v0.w;
        acc4 += a * v1.x; acc5 += a * v1.y; acc6 += a * v1.z; acc7 += a * v1.w;
        dsum += a;
        j = jn; a = an; ++e;
    }
    float inv = 1.0f / (dsum + 1e-9f);
    float* d = agg + (size_t)w * HD + lane * 8;
    *(float4*)(d)     = make_float4(acc0 * inv, acc1 * inv, acc2 * inv, acc3 * inv);
    *(float4*)(d + 4) = make_float4(acc4 * inv, acc5 * inv, acc6 * inv, acc7 * inv);
}

// ---------------- GEMM2 (tf32 mma): out = LN(ELU(agg @ W_out^T + b) + x) ----------------
// Block: 128 rows x 64 cols. K=256 in 4 chunks of 64.
__global__ __launch_bounds__(256) void k_gemm2(
    const float* __restrict__ A,     // agg [M,256]
    const float* __restrict__ B,     // W_out [64,256]
    const float* __restrict__ x,
    const float* __restrict__ bias,
    const float* __restrict__ lng, const float* __restrict__ lnb,
    float* __restrict__ out, int M)
{
    extern __shared__ float sm[];
    float* As = sm;                  // [128][PAD]
    float* Bs = sm + AS_FLOATS;      // [64][PAD]
    const int t    = threadIdx.x;
    const int lane = t & 31;
    const int w    = t >> 5;
    const int gid  = lane >> 2;
    const int tid4 = lane & 3;
    const int m0   = blockIdx.x * 128;

    float acc[8][4] = {};
    const int r0 = w * 16 + gid;
    const int r1 = r0 + 8;

    for (int kc = 0; kc < HD; kc += 64) {
        #pragma unroll
        for (int it = 0; it < 8; ++it) {
            int idx = t + it * 256;
            int row = idx >> 4;
            int k4  = (idx & 15) * 4;
            float4 v = make_float4(0.f, 0.f, 0.f, 0.f);
            int gr = m0 + row;
            if (gr < M) v = *(const float4*)(A + (size_t)gr * HD + kc + k4);
            *(float4*)&As[row * PAD + k4] = v;
        }
        #pragma unroll
        for (int it = 0; it < 4; ++it) {
            int idx = t + it * 256;
            int nr  = idx >> 4;
            int k4  = (idx & 15) * 4;
            *(float4*)&Bs[nr * PAD + k4] = *(const float4*)(B + (size_t)nr * HD + kc + k4);
        }
        __syncthreads();

        #pragma unroll
        for (int ks = 0; ks < 8; ++ks) {
            int c0 = ks * 8 + tid4;
            int c1 = c0 + 4;
            uint32_t ah[4], al[4];
            hilo(As[r0 * PAD + c0], ah[0], al[0]);
            hilo(As[r1 * PAD + c0], ah[1], al[1]);
            hilo(As[r0 * PAD + c1], ah[2], al[2]);
            hilo(As[r1 * PAD + c1], ah[3], al[3]);
            #pragma unroll
            for (int nt = 0; nt < 8; ++nt) {
                uint32_t bh0, bl0, bh1, bl1;
                hilo(Bs[(nt * 8 + gid) * PAD + c0], bh0, bl0);
                hilo(Bs[(nt * 8 + gid) * PAD + c1], bh1, bl1);
                mma_tf32(acc[nt][0], acc[nt][1], acc[nt][2], acc[nt][3],
                         ah[0], ah[1], ah[2], ah[3], bh0, bh1);
                mma_tf32(acc[nt][0], acc[nt][1], acc[nt][2], acc[nt][3],
                         ah[0], ah[1], ah[2], ah[3], bl0, bl1);
                mma_tf32(acc[nt][0], acc[nt][1], acc[nt][2], acc[nt][3],
                         al[0], al[1], al[2], al[3], bh0, bh1);
            }
        }
        __syncthreads();
    }

    // epilogue: bias + ELU + residual + LayerNorm; two rows per thread
    int gr0 = m0 + r0;
    int gr1 = m0 + r1;
    float y0[16], y1[16];
    float s0 = 0.f, q0 = 0.f, s1 = 0.f, q1 = 0.f;
    #pragma unroll
    for (int nt = 0; nt < 8; ++nt) {
        int col = nt * 8 + tid4 * 2;
        float2 bb = __ldg((const float2*)(bias + col));
        float2 x0 = (gr0 < M) ? *(const float2*)(x + (size_t)gr0 * DIM + col) : make_float2(0.f, 0.f);
        float2 x1 = (gr1 < M) ? *(const float2*)(x + (size_t)gr1 * DIM + col) : make_float2(0.f, 0.f);
        float v;
        v = acc[nt][0] + bb.x; v = v > 0.f ? v : (expf(v) - 1.f); y0[nt*2+0] = v + x0.x;
        v = acc[nt][1] + bb.y; v = v > 0.f ? v : (expf(v) - 1.f); y0[nt*2+1] = v + x0.y;
        v = acc[nt][2] + bb.x; v = v > 0.f ? v : (expf(v) - 1.f); y1[nt*2+0] = v + x1.x;
        v = acc[nt][3] + bb.y; v = v > 0.f ? v : (expf(v) - 1.f); y1[nt*2+1] = v + x1.y;
        s0 += y0[nt*2+0] + y0[nt*2+1]; q0 += y0[nt*2+0]*y0[nt*2+0] + y0[nt*2+1]*y0[nt*2+1];
        s1 += y1[nt*2+0] + y1[nt*2+1]; q1 += y1[nt*2+0]*y1[nt*2+0] + y1[nt*2+1]*y1[nt*2+1];
    }
    #pragma unroll
    for (int o = 1; o < 4; o <<= 1) {
        s0 += __shfl_xor_sync(0xffffffffu, s0, o);
        q0 += __shfl_xor_sync(0xffffffffu, q0, o);
        s1 += __shfl_xor_sync(0xffffffffu, s1, o);
        q1 += __shfl_xor_sync(0xffffffffu, q1, o);
    }
    float mu0  = s0 * (1.0f / 64.0f);
    float var0 = q0 * (1.0f / 64.0f) - mu0 * mu0;
    float inv0 = rsqrtf(var0 + 1e-5f);
    float mu1  = s1 * (1.0f / 64.0f);
    float var1 = q1 * (1.0f / 64.0f) - mu1 * mu1;
    float inv1 = rsqrtf(var1 + 1e-5f);
    #pragma unroll
    for (int nt = 0; nt < 8; ++nt) {
        int col = nt * 8 + tid4 * 2;
        float2 gg = __ldg((const float2*)(lng + col));
        float2 lb = __ldg((const float2*)(lnb + col));
        if (gr0 < M) {
            float2 o0;
            o0.x = (y0[nt*2+0] - mu0) * inv0 * gg.x + lb.x;
            o0.y = (y0[nt*2+1] - mu0) * inv0 * gg.y + lb.y;
            *(float2*)(out + (size_t)gr0 * DIM + col) = o0;
        }
        if (gr1 < M) {
            float2 o1;
            o1.x = (y1[nt*2+0] - mu1) * inv1 * gg.x + lb.x;
            o1.y = (y1[nt*2+1] - mu1) * inv1 * gg.y + lb.y;
            *(float2*)(out + (size_t)gr1 * DIM + col) = o1;
        }
    }
}

// ---------------- launch ----------------
extern "C" void kernel_launch(void* const* d_in, const int* in_sizes, int n_in,
                              void* d_out, int out_size)
{
    const float* x    = (const float*)d_in[0];
    const int*   ei   = (const int*)d_in[1];   // int32 [2,E]
    const float* Wlin = (const float*)d_in[2];
    const float* asrc = (const float*)d_in[3];
    const float* adst = (const float*)d_in[4];
    const float* Wout = (const float*)d_in[5];
    const float* bout = (const float*)d_in[6];
    const float* lng  = (const float*)d_in[7];
    const float* lnb  = (const float*)d_in[8];
    float*       out  = (float*)d_out;

    int n = in_sizes[0] / DIM;
    int E = in_sizes[1] / 2;
    if (n > NMAX) n = NMAX;
    if (E > EMAX) E = EMAX;

    float *p_xh, *p_agg, *p_ssrc, *p_sdst, *p_ealpha;
    int *p_cnt, *p_off, *p_cursor, *p_esrc;
    cudaGetSymbolAddress((void**)&p_xh,     g_xh);
    cudaGetSymbolAddress((void**)&p_agg,    g_agg);
    cudaGetSymbolAddress((void**)&p_ssrc,   g_ssrc);
    cudaGetSymbolAddress((void**)&p_sdst,   g_sdst);
    cudaGetSymbolAddress((void**)&p_cnt,    g_cnt);
    cudaGetSymbolAddress((void**)&p_off,    g_off);
    cudaGetSymbolAddress((void**)&p_cursor, g_cursor);
    cudaGetSymbolAddress((void**)&p_esrc,   g_esrc);
    cudaGetSymbolAddress((void**)&p_ealpha, g_ealpha);

    cudaFuncSetAttribute(k_gemm1, cudaFuncAttributeMaxDynamicSharedMemorySize, GEMM_SMEM_B);
    cudaFuncSetAttribute(k_gemm2, cudaFuncAttributeMaxDynamicSharedMemorySize, GEMM_SMEM_B);

    // 1) dst-degree histogram
    k_hzero<<<(n + 255) / 256, 256>>>(p_cnt, n);
    k_hist <<<(E + 255) / 256, 256>>>(ei, p_cnt, E);

    // 2) CSR offsets
    k_scan<<<1, 1024>>>(p_cnt, p_off, p_cursor, n);

    // 3) xh = x @ W_lin^T with fused scores (tf32 mma, 3xTF32)
    dim3 g1((n + 127) / 128, HEADS);
    k_gemm1<<<g1, 256, GEMM_SMEM_B>>>(x, Wlin, asrc, adst, p_xh, p_ssrc, p_sdst, n);

    // 4) scatter edges (dst-sorted) with inline alpha
    k_scatter<<<(E + 255) / 256, 256>>>(ei, p_ssrc, p_sdst, p_cursor, p_esrc, p_ealpha, E);

    // 5) pull aggregation
    k_agg_csr<<<(n * 32 + 255) / 256, 256>>>(p_off, p_esrc, p_ealpha, p_xh, p_agg, n);

    // 6) out = LN(ELU(agg @ W_out^T + b) + x) (tf32 mma, 3xTF32)
    k_gemm2<<<(n + 127) / 128, 256, GEMM_SMEM_B>>>(p_agg, Wout, x, bout, lng, lnb, out, n);
}

// round 12
// speedup vs baseline: 1.3112x; 1.0016x over previous
#include <cuda_runtime.h>
#include <cstdint>

#define NMAX 50000
#define EMAX 400000
#define HEADS 4
#define DIM 64
#define HD 256   // HEADS*DIM

#define PAD 68                        // padded row length
#define AS_FLOATS (128 * PAD)         // A tile (float)
#define BS_WORDS  (64 * PAD)          // one B plane (uint32)
#define GEMM_SMEM_B ((AS_FLOATS + 2 * BS_WORDS) * 4)   // 69,632 bytes

// ---------------- scratch (device globals; no allocation) ----------------
__device__ float g_xh    [(size_t)NMAX * HD];
__device__ float g_agg   [(size_t)NMAX * HD];
__device__ float g_ssrc  [(size_t)NMAX * HEADS];
__device__ float g_sdst  [(size_t)NMAX * HEADS];
__device__ int   g_cnt   [NMAX];
__device__ int   g_off   [NMAX + 1];
__device__ int   g_cursor[NMAX];
__device__ int   g_esrc  [EMAX];
__device__ float g_ealpha[(size_t)EMAX * HEADS];

// ---------------- tf32 mma helpers ----------------
__device__ __forceinline__ uint32_t f2tf32(float x) {
    uint32_t r;
    asm("cvt.rna.tf32.f32 %0, %1;" : "=r"(r) : "f"(x));
    return r;
}
__device__ __forceinline__ void hilo(float v, uint32_t& hi, uint32_t& lo) {
    hi = f2tf32(v);
    lo = f2tf32(v - __uint_as_float(hi));
}
__device__ __forceinline__ void mma_tf32(float& d0, float& d1, float& d2, float& d3,
                                         uint32_t a0, uint32_t a1, uint32_t a2, uint32_t a3,
                                         uint32_t b0, uint32_t b1) {
    asm("mma.sync.aligned.m16n8k8.row.col.f32.tf32.tf32.f32 "
        "{%0,%1,%2,%3}, {%4,%5,%6,%7}, {%8,%9}, {%0,%1,%2,%3};"
        : "+f"(d0), "+f"(d1), "+f"(d2), "+f"(d3)
        : "r"(a0), "r"(a1), "r"(a2), "r"(a3), "r"(b0), "r"(b1));
}

// ---------------- zero histogram ----------------
__global__ void k_hzero(int* __restrict__ cnt, int n) {
    int i = blockIdx.x * blockDim.x + threadIdx.x;
    if (i < n) cnt[i] = 0;
}

// ---------------- histogram of dst ----------------
__global__ void k_hist(const int* __restrict__ ei, int* __restrict__ cnt, int E) {
    int e = blockIdx.x * blockDim.x + threadIdx.x;
    if (e < E) atomicAdd(&cnt[ei[e]], 1);
}

// ---------------- single-block exclusive scan ----------------
__global__ __launch_bounds__(1024) void k_scan(const int* __restrict__ cnt,
                                               int* __restrict__ off,
                                               int* __restrict__ cursor, int n)
{
    __shared__ int warpsum[32];
    const int tid  = threadIdx.x;
    const int lane = tid & 31;
    const int wid  = tid >> 5;
    int base = 0;
    for (int chunk = 0; chunk < n; chunk += 1024) {
        int idx = chunk + tid;
        int v = (idx < n) ? cnt[idx] : 0;
        int x = v;
        #pragma unroll
        for (int o = 1; o < 32; o <<= 1) {
            int y = __shfl_up_sync(0xffffffffu, x, o);
            if (lane >= o) x += y;
        }
        if (lane == 31) warpsum[wid] = x;
        __syncthreads();
        if (wid == 0) {
            int w = (lane < 32) ? warpsum[lane] : 0;
            #pragma unroll
            for (int o = 1; o < 32; o <<= 1) {
                int y = __shfl_up_sync(0xffffffffu, w, o);
                if (lane >= o) w += y;
            }
            warpsum[lane] = w;
        }
        __syncthreads();
        int excl = x - v + (wid > 0 ? warpsum[wid - 1] : 0) + base;
        if (idx < n) { off[idx] = excl; cursor[idx] = excl; }
        int total = warpsum[31];
        __syncthreads();
        base += total;
    }
    if (tid == 0) off[n] = base;
}

// ---------------- GEMM1 (tf32 mma, B hi/lo precomputed): xh = x @ W_lin^T + scores ----------------
__global__ __launch_bounds__(256) void k_gemm1(
    const float* __restrict__ A,     // x [M,64]
    const float* __restrict__ B,     // W_lin [256,64]
    const float* __restrict__ asrc, const float* __restrict__ adst,
    float* __restrict__ C,           // xh [M,256]
    float* __restrict__ ssrc, float* __restrict__ sdst, int M)
{
    extern __shared__ float sm[];
    float*    As  = sm;                                  // [128][PAD] float
    uint32_t* Bhi = (uint32_t*)(sm + AS_FLOATS);         // [64][PAD]
    uint32_t* Blo = Bhi + BS_WORDS;                      // [64][PAD]
    const int t    = threadIdx.x;
    const int lane = t & 31;
    const int w    = t >> 5;
    const int gid  = lane >> 2;
    const int tid4 = lane & 3;
    const int m0   = blockIdx.x * 128;
    const int h    = blockIdx.y;
    const float* Bt = B + (size_t)h * 64 * DIM;

    // fill A tile [128][64]
    #pragma unroll
    for (int it = 0; it < 8; ++it) {
        int idx = t + it * 256;
        int row = idx >> 4;
        int k4  = (idx & 15) * 4;
        float4 v = make_float4(0.f, 0.f, 0.f, 0.f);
        int gr = m0 + row;
        if (gr < M) v = *(const float4*)(A + (size_t)gr * DIM + k4);
        *(float4*)&As[row * PAD + k4] = v;
    }
    // fill B tile [64][64], converted to tf32 hi/lo once
    #pragma unroll
    for (int it = 0; it < 4; ++it) {
        int idx = t + it * 256;
        int nr  = idx >> 4;
        int k4  = (idx & 15) * 4;
        float4 v = *(const float4*)(Bt + (size_t)nr * DIM + k4);
        uint32_t hh, ll;
        hilo(v.x, hh, ll); Bhi[nr * PAD + k4 + 0] = hh; Blo[nr * PAD + k4 + 0] = ll;
        hilo(v.y, hh, ll); Bhi[nr * PAD + k4 + 1] = hh; Blo[nr * PAD + k4 + 1] = ll;
        hilo(v.z, hh, ll); Bhi[nr * PAD + k4 + 2] = hh; Blo[nr * PAD + k4 + 2] = ll;
        hilo(v.w, hh, ll); Bhi[nr * PAD + k4 + 3] = hh; Blo[nr * PAD + k4 + 3] = ll;
    }
    __syncthreads();

    float acc[8][4] = {};
    const int r0 = w * 16 + gid;
    const int r1 = r0 + 8;

    #pragma unroll
    for (int ks = 0; ks < 8; ++ks) {
        int c0 = ks * 8 + tid4;
        int c1 = c0 + 4;
        uint32_t ah[4], al[4];
        hilo(As[r0 * PAD + c0], ah[0], al[0]);
        hilo(As[r1 * PAD + c0], ah[1], al[1]);
        hilo(As[r0 * PAD + c1], ah[2], al[2]);
        hilo(As[r1 * PAD + c1], ah[3], al[3]);
        #pragma unroll
        for (int nt = 0; nt < 8; ++nt) {
            int bi = (nt * 8 + gid) * PAD;
            uint32_t bh0 = Bhi[bi + c0], bl0 = Blo[bi + c0];
            uint32_t bh1 = Bhi[bi + c1], bl1 = Blo[bi + c1];
            mma_tf32(acc[nt][0], acc[nt][1], acc[nt][2], acc[nt][3],
                     ah[0], ah[1], ah[2], ah[3], bh0, bh1);
            mma_tf32(acc[nt][0], acc[nt][1], acc[nt][2], acc[nt][3],
                     ah[0], ah[1], ah[2], ah[3], bl0, bl1);
            mma_tf32(acc[nt][0], acc[nt][1], acc[nt][2], acc[nt][3],
                     al[0], al[1], al[2], al[3], bh0, bh1);
        }
    }

    // epilogue: store xh + fused per-row scores
    int gr0 = m0 + r0;
    int gr1 = m0 + r1;
    float ss0 = 0.f, sd0 = 0.f, ss1 = 0.f, sd1 = 0.f;
    #pragma unroll
    for (int nt = 0; nt < 8; ++nt) {
        int col = nt * 8 + tid4 * 2;
        float2 av = __ldg((const float2*)(asrc + h * DIM + col));
        float2 dv = __ldg((const float2*)(adst + h * DIM + col));
        if (gr0 < M)
            *(float2*)(C + (size_t)gr0 * HD + h * 64 + col) = make_float2(acc[nt][0], acc[nt][1]);
        if (gr1 < M)
            *(float2*)(C + (size_t)gr1 * HD + h * 64 + col) = make_float2(acc[nt][2], acc[nt][3]);
        ss0 += acc[nt][0] * av.x + acc[nt][1] * av.y;
        sd0 += acc[nt][0] * dv.x + acc[nt][1] * dv.y;
        ss1 += acc[nt][2] * av.x + acc[nt][3] * av.y;
        sd1 += acc[nt][2] * dv.x + acc[nt][3] * dv.y;
    }
    #pragma unroll
    for (int o = 1; o < 4; o <<= 1) {
        ss0 += __shfl_xor_sync(0xffffffffu, ss0, o);
        sd0 += __shfl_xor_sync(0xffffffffu, sd0, o);
        ss1 += __shfl_xor_sync(0xffffffffu, ss1, o);
        sd1 += __shfl_xor_sync(0xffffffffu, sd1, o);
    }
    if (tid4 == 0) {
        if (gr0 < M) {
            ssrc[(size_t)gr0 * HEADS + h] = ss0;
            sdst[(size_t)gr0 * HEADS + h] = sd0;
        }
        if (gr1 < M) {
            ssrc[(size_t)gr1 * HEADS + h] = ss1;
            sdst[(size_t)gr1 * HEADS + h] = sd1;
        }
    }
}

// ---------------- scatter edges into dst-sorted order, alpha inline ----------------
__global__ void k_scatter(const int* __restrict__ ei,
                          const float* __restrict__ ssrc, const float* __restrict__ sdst,
                          int* __restrict__ cursor,
                          int* __restrict__ esrc, float* __restrict__ ealpha, int E)
{
    int e = blockIdx.x * blockDim.x + threadIdx.x;
    if (e >= E) return;
    int i = ei[e];        // dst
    int j = ei[E + e];    // src
    float4 sd = *(const float4*)(sdst + (size_t)i * 4);
    float4 ss = *(const float4*)(ssrc + (size_t)j * 4);
    float a0 = sd.x + ss.x; a0 = a0 > 0.f ? a0 : 0.2f * a0;
    float a1 = sd.y + ss.y; a1 = a1 > 0.f ? a1 : 0.2f * a1;
    float a2 = sd.z + ss.z; a2 = a2 > 0.f ? a2 : 0.2f * a2;
    float a3 = sd.w + ss.w; a3 = a3 > 0.f ? a3 : 0.2f * a3;
    int pos = atomicAdd(&cursor[i], 1);
    esrc[pos] = j;
    *(float4*)(ealpha + (size_t)pos * 4) =
        make_float4(expf(a0), expf(a1), expf(a2), expf(a3));
}

// ---------------- CSR aggregation: one warp per dst node ----------------
__global__ __launch_bounds__(256) void k_agg_csr(
    const int* __restrict__ off, const int* __restrict__ esrc,
    const float* __restrict__ ealpha, const float* __restrict__ xh,
    float* __restrict__ agg, int n)
{
    int w    = (blockIdx.x * blockDim.x + threadIdx.x) >> 5;
    int lane = threadIdx.x & 31;
    if (w >= n) return;
    int beg = off[w], end = off[w + 1];
    int head = lane >> 3;
    float acc0 = 0.f, acc1 = 0.f, acc2 = 0.f, acc3 = 0.f;
    float acc4 = 0.f, acc5 = 0.f, acc6 = 0.f, acc7 = 0.f;
    float dsum = 0.f;

    int e = beg;
    int j = 0; float a = 0.f;
    if (e < end) { j = esrc[e]; a = ealpha[(size_t)e * 4 + head]; }
    while (e < end) {
        int jn = 0; float an = 0.f;
        if (e + 1 < end) { jn = esrc[e + 1]; an = ealpha[(size_t)(e + 1) * 4 + head]; }
        const float* s = xh + (size_t)j * HD + lane * 8;
        float4 v0 = *(const float4*)(s);
        float4 v1 = *(const float4*)(s + 4);
        acc0 += a * v0.x; acc1 += a * v0.y; acc2 += a * v0.z; acc3 += a * v0.w;
        acc4 += a * v1.x; acc5 += a * v1.y; acc6 += a * v1.z; acc7 += a * v1.w;
        dsum += a;
        j = jn; a = an; ++e;
    }
    float inv = 1.0f / (dsum + 1e-9f);
    float* d = agg + (size_t)w * HD + lane * 8;
    *(float4*)(d)     = make_float4(acc0 * inv, acc1 * inv, acc2 * inv, acc3 * inv);
    *(float4*)(d + 4) = make_float4(acc4 * inv, acc5 * inv, acc6 * inv, acc7 * inv);
}

// ---------------- GEMM2 (tf32 mma, B hi/lo precomputed): out = LN(ELU(agg@W_out^T+b)+x) ----------------
__global__ __launch_bounds__(256) void k_gemm2(
    const float* __restrict__ A,     // agg [M,256]
    const float* __restrict__ B,     // W_out [64,256]
    const float* __restrict__ x,
    const float* __restrict__ bias,
    const float* __restrict__ lng, const float* __restrict__ lnb,
    float* __restrict__ out, int M)
{
    extern __shared__ float sm[];
    float*    As  = sm;                                  // [128][PAD]
    uint32_t* Bhi = (uint32_t*)(sm + AS_FLOATS);
    uint32_t* Blo = Bhi + BS_WORDS;
    const int t    = threadIdx.x;
    const int lane = t & 31;
    const int w    = t >> 5;
    const int gid  = lane >> 2;
    const int tid4 = lane & 3;
    const int m0   = blockIdx.x * 128;

    float acc[8][4] = {};
    const int r0 = w * 16 + gid;
    const int r1 = r0 + 8;

    for (int kc = 0; kc < HD; kc += 64) {
        #pragma unroll
        for (int it = 0; it < 8; ++it) {
            int idx = t + it * 256;
            int row = idx >> 4;
            int k4  = (idx & 15) * 4;
            float4 v = make_float4(0.f, 0.f, 0.f, 0.f);
            int gr = m0 + row;
            if (gr < M) v = *(const float4*)(A + (size_t)gr * HD + kc + k4);
            *(float4*)&As[row * PAD + k4] = v;
        }
        #pragma unroll
        for (int it = 0; it < 4; ++it) {
            int idx = t + it * 256;
            int nr  = idx >> 4;
            int k4  = (idx & 15) * 4;
            float4 v = *(const float4*)(B + (size_t)nr * HD + kc + k4);
            uint32_t hh, ll;
            hilo(v.x, hh, ll); Bhi[nr * PAD + k4 + 0] = hh; Blo[nr * PAD + k4 + 0] = ll;
            hilo(v.y, hh, ll); Bhi[nr * PAD + k4 + 1] = hh; Blo[nr * PAD + k4 + 1] = ll;
            hilo(v.z, hh, ll); Bhi[nr * PAD + k4 + 2] = hh; Blo[nr * PAD + k4 + 2] = ll;
            hilo(v.w, hh, ll); Bhi[nr * PAD + k4 + 3] = hh; Blo[nr * PAD + k4 + 3] = ll;
        }
        __syncthreads();

        #pragma unroll
        for (int ks = 0; ks < 8; ++ks) {
            int c0 = ks * 8 + tid4;
            int c1 = c0 + 4;
            uint32_t ah[4], al[4];
            hilo(As[r0 * PAD + c0], ah[0], al[0]);
            hilo(As[r1 * PAD + c0], ah[1], al[1]);
            hilo(As[r0 * PAD + c1], ah[2], al[2]);
            hilo(As[r1 * PAD + c1], ah[3], al[3]);
            #pragma unroll
            for (int nt = 0; nt < 8; ++nt) {
                int bi = (nt * 8 + gid) * PAD;
                uint32_t bh0 = Bhi[bi + c0], bl0 = Blo[bi + c0];
                uint32_t bh1 = Bhi[bi + c1], bl1 = Blo[bi + c1];
                mma_tf32(acc[nt][0], acc[nt][1], acc[nt][2], acc[nt][3],
                         ah[0], ah[1], ah[2], ah[3], bh0, bh1);
                mma_tf32(acc[nt][0], acc[nt][1], acc[nt][2], acc[nt][3],
                         ah[0], ah[1], ah[2], ah[3], bl0, bl1);
                mma_tf32(acc[nt][0], acc[nt][1], acc[nt][2], acc[nt][3],
                         al[0], al[1], al[2], al[3], bh0, bh1);
            }
        }
        __syncthreads();
    }

    // epilogue: bias + ELU + residual + LayerNorm; two rows per thread
    int gr0 = m0 + r0;
    int gr1 = m0 + r1;
    float y0[16], y1[16];
    float s0 = 0.f, q0 = 0.f, s1 = 0.f, q1 = 0.f;
    #pragma unroll
    for (int nt = 0; nt < 8; ++nt) {
        int col = nt * 8 + tid4 * 2;
        float2 bb = __ldg((const float2*)(bias + col));
        float2 x0 = (gr0 < M) ? *(const float2*)(x + (size_t)gr0 * DIM + col) : make_float2(0.f, 0.f);
        float2 x1 = (gr1 < M) ? *(const float2*)(x + (size_t)gr1 * DIM + col) : make_float2(0.f, 0.f);
        float v;
        v = acc[nt][0] + bb.x; v = v > 0.f ? v : (expf(v) - 1.f); y0[nt*2+0] = v + x0.x;
        v = acc[nt][1] + bb.y; v = v > 0.f ? v : (expf(v) - 1.f); y0[nt*2+1] = v + x0.y;
        v = acc[nt][2] + bb.x; v = v > 0.f ? v : (expf(v) - 1.f); y1[nt*2+0] = v + x1.x;
        v = acc[nt][3] + bb.y; v = v > 0.f ? v : (expf(v) - 1.f); y1[nt*2+1] = v + x1.y;
        s0 += y0[nt*2+0] + y0[nt*2+1]; q0 += y0[nt*2+0]*y0[nt*2+0] + y0[nt*2+1]*y0[nt*2+1];
        s1 += y1[nt*2+0] + y1[nt*2+1]; q1 += y1[nt*2+0]*y1[nt*2+0] + y1[nt*2+1]*y1[nt*2+1];
    }
    #pragma unroll
    for (int o = 1; o < 4; o <<= 1) {
        s0 += __shfl_xor_sync(0xffffffffu, s0, o);
        q0 += __shfl_xor_sync(0xffffffffu, q0, o);
        s1 += __shfl_xor_sync(0xffffffffu, s1, o);
        q1 += __shfl_xor_sync(0xffffffffu, q1, o);
    }
    float mu0  = s0 * (1.0f / 64.0f);
    float var0 = q0 * (1.0f / 64.0f) - mu0 * mu0;
    float inv0 = rsqrtf(var0 + 1e-5f);
    float mu1  = s1 * (1.0f / 64.0f);
    float var1 = q1 * (1.0f / 64.0f) - mu1 * mu1;
    float inv1 = rsqrtf(var1 + 1e-5f);
    #pragma unroll
    for (int nt = 0; nt < 8; ++nt) {
        int col = nt * 8 + tid4 * 2;
        float2 gg = __ldg((const float2*)(lng + col));
        float2 lb = __ldg((const float2*)(lnb + col));
        if (gr0 < M) {
            float2 o0;
            o0.x = (y0[nt*2+0] - mu0) * inv0 * gg.x + lb.x;
            o0.y = (y0[nt*2+1] - mu0) * inv0 * gg.y + lb.y;
            *(float2*)(out + (size_t)gr0 * DIM + col) = o0;
        }
        if (gr1 < M) {
            float2 o1;
            o1.x = (y1[nt*2+0] - mu1) * inv1 * gg.x + lb.x;
            o1.y = (y1[nt*2+1] - mu1) * inv1 * gg.y + lb.y;
            *(float2*)(out + (size_t)gr1 * DIM + col) = o1;
        }
    }
}

// ---------------- launch ----------------
extern "C" void kernel_launch(void* const* d_in, const int* in_sizes, int n_in,
                              void* d_out, int out_size)
{
    const float* x    = (const float*)d_in[0];
    const int*   ei   = (const int*)d_in[1];   // int32 [2,E]
    const float* Wlin = (const float*)d_in[2];
    const float* asrc = (const float*)d_in[3];
    const float* adst = (const float*)d_in[4];
    const float* Wout = (const float*)d_in[5];
    const float* bout = (const float*)d_in[6];
    const float* lng  = (const float*)d_in[7];
    const float* lnb  = (const float*)d_in[8];
    float*       out  = (float*)d_out;

    int n = in_sizes[0] / DIM;
    int E = in_sizes[1] / 2;
    if (n > NMAX) n = NMAX;
    if (E > EMAX) E = EMAX;

    float *p_xh, *p_agg, *p_ssrc, *p_sdst, *p_ealpha;
    int *p_cnt, *p_off, *p_cursor, *p_esrc;
    cudaGetSymbolAddress((void**)&p_xh,     g_xh);
    cudaGetSymbolAddress((void**)&p_agg,    g_agg);
    cudaGetSymbolAddress((void**)&p_ssrc,   g_ssrc);
    cudaGetSymbolAddress((void**)&p_sdst,   g_sdst);
    cudaGetSymbolAddress((void**)&p_cnt,    g_cnt);
    cudaGetSymbolAddress((void**)&p_off,    g_off);
    cudaGetSymbolAddress((void**)&p_cursor, g_cursor);
    cudaGetSymbolAddress((void**)&p_esrc,   g_esrc);
    cudaGetSymbolAddress((void**)&p_ealpha, g_ealpha);

    cudaFuncSetAttribute(k_gemm1, cudaFuncAttributeMaxDynamicSharedMemorySize, GEMM_SMEM_B);
    cudaFuncSetAttribute(k_gemm2, cudaFuncAttributeMaxDynamicSharedMemorySize, GEMM_SMEM_B);

    // 1) dst-degree histogram
    k_hzero<<<(n + 255) / 256, 256>>>(p_cnt, n);
    k_hist <<<(E + 255) / 256, 256>>>(ei, p_cnt, E);

    // 2) CSR offsets
    k_scan<<<1, 1024>>>(p_cnt, p_off, p_cursor, n);

    // 3) xh = x @ W_lin^T with fused scores (tf32 mma, B hi/lo in smem)
    dim3 g1((n + 127) / 128, HEADS);
    k_gemm1<<<g1, 256, GEMM_SMEM_B>>>(x, Wlin, asrc, adst, p_xh, p_ssrc, p_sdst, n);

    // 4) scatter edges (dst-sorted) with inline alpha
    k_scatter<<<(E + 255) / 256, 256>>>(ei, p_ssrc, p_sdst, p_cursor, p_esrc, p_ealpha, E);

    // 5) pull aggregation
    k_agg_csr<<<(n * 32 + 255) / 256, 256>>>(p_off, p_esrc, p_ealpha, p_xh, p_agg, n);

    // 6) out = LN(ELU(agg @ W_out^T + b) + x) (tf32 mma, B hi/lo in smem)
    k_gemm2<<<(n + 127) / 128, 256, GEMM_SMEM_B>>>(p_agg, Wout, x, bout, lng, lnb, out, n);
}

// round 14
// speedup vs baseline: 1.6113x; 1.2289x over previous
#include <cuda_runtime.h>
#include <cstdint>

#define NMAX 50000
#define EMAX 400000
#define HEADS 4
#define DIM 64
#define HD 256   // HEADS*DIM

#define PAD 68                        // padded row length
#define AS_FLOATS (128 * PAD)         // A tile (float)
#define BS_WORDS  (64 * PAD)          // one B plane (uint32)
#define GEMM_SMEM_B ((AS_FLOATS + 2 * BS_WORDS) * 4)   // 69,632 bytes

// ---------------- scratch (device globals; no allocation) ----------------
__device__ float g_agg   [(size_t)NMAX * HD];     // per-head weighted x sums [N,4,64]
__device__ float g_ssrc  [(size_t)NMAX * HEADS];
__device__ float g_sdst  [(size_t)NMAX * HEADS];
__device__ int   g_cnt   [NMAX];
__device__ int   g_off   [NMAX + 1];
__device__ int   g_cursor[NMAX];
__device__ int   g_esrc  [EMAX];
__device__ float g_ealpha[(size_t)EMAX * HEADS];
__device__ float g_wc    [64 * HD];               // folded weight [64 d][256]
__device__ float g_vv    [8 * DIM];               // score vectors: src h0-3, dst h0-3

// ---------------- tf32 mma helpers ----------------
__device__ __forceinline__ uint32_t f2tf32(float x) {
    uint32_t r;
    asm("cvt.rna.tf32.f32 %0, %1;" : "=r"(r) : "f"(x));
    return r;
}
__device__ __forceinline__ void hilo(float v, uint32_t& hi, uint32_t& lo) {
    hi = f2tf32(v);
    lo = f2tf32(v - __uint_as_float(hi));
}
__device__ __forceinline__ void mma_tf32(float& d0, float& d1, float& d2, float& d3,
                                         uint32_t a0, uint32_t a1, uint32_t a2, uint32_t a3,
                                         uint32_t b0, uint32_t b1) {
    asm("mma.sync.aligned.m16n8k8.row.col.f32.tf32.tf32.f32 "
        "{%0,%1,%2,%3}, {%4,%5,%6,%7}, {%8,%9}, {%0,%1,%2,%3};"
        : "+f"(d0), "+f"(d1), "+f"(d2), "+f"(d3)
        : "r"(a0), "r"(a1), "r"(a2), "r"(a3), "r"(b0), "r"(b1));
}

// ---------------- zero histogram ----------------
__global__ void k_hzero(int* __restrict__ cnt, int n) {
    int i = blockIdx.x * blockDim.x + threadIdx.x;
    if (i < n) cnt[i] = 0;
}

// ---------------- histogram of dst ----------------
__global__ void k_hist(const int* __restrict__ ei, int* __restrict__ cnt, int E) {
    int e = blockIdx.x * blockDim.x + threadIdx.x;
    if (e < E) atomicAdd(&cnt[ei[e]], 1);
}

// ---------------- single-block exclusive scan ----------------
__global__ __launch_bounds__(1024) void k_scan(const int* __restrict__ cnt,
                                               int* __restrict__ off,
                                               int* __restrict__ cursor, int n)
{
    __shared__ int warpsum[32];
    const int tid  = threadIdx.x;
    const int lane = tid & 31;
    const int wid  = tid >> 5;
    int base = 0;
    for (int chunk = 0; chunk < n; chunk += 1024) {
        int idx = chunk + tid;
        int v = (idx < n) ? cnt[idx] : 0;
        int x = v;
        #pragma unroll
        for (int o = 1; o < 32; o <<= 1) {
            int y = __shfl_up_sync(0xffffffffu, x, o);
            if (lane >= o) x += y;
        }
        if (lane == 31) warpsum[wid] = x;
        __syncthreads();
        if (wid == 0) {
            int w = (lane < 32) ? warpsum[lane] : 0;
            #pragma unroll
            for (int o = 1; o < 32; o <<= 1) {
                int y = __shfl_up_sync(0xffffffffu, w, o);
                if (lane >= o) w += y;
            }
            warpsum[lane] = w;
        }
        __syncthreads();
        int excl = x - v + (wid > 0 ? warpsum[wid - 1] : 0) + base;
        if (idx < n) { off[idx] = excl; cursor[idx] = excl; }
        int total = warpsum[31];
        __syncthreads();
        base += total;
    }
    if (tid == 0) off[n] = base;
}

// ---------------- prep: fold weights Wc = W_out_h @ W_h, score vectors v = W_h^T a ----------------
// One block per head (grid=4, 256 threads).
__global__ __launch_bounds__(256) void k_prep(
    const float* __restrict__ Wlin,  // [256,64]
    const float* __restrict__ Wout,  // [64,256]
    const float* __restrict__ asrc, const float* __restrict__ adst,
    float* __restrict__ wc, float* __restrict__ vv)
{
    __shared__ float Wl[64][65];   // Wl[c][k] = W_lin[h*64+c][k]
    __shared__ float Wo[64][65];   // Wo[d][c] = W_out[d][h*64+c]
    const int h = blockIdx.x;
    const int t = threadIdx.x;
    #pragma unroll
    for (int it = 0; it < 16; ++it) {
        int idx = t + it * 256;
        int r = idx >> 6, c = idx & 63;
        Wl[r][c] = Wlin[(size_t)(h * 64 + r) * DIM + c];
        Wo[r][c] = Wout[(size_t)r * HD + h * 64 + c];
    }
    __syncthreads();

    // Wc[d][h*64+k] = sum_c Wo[d][c] * Wl[c][k]
    int d = t >> 2, ks0 = (t & 3) * 16;
    float accv[16] = {};
    for (int c = 0; c < 64; ++c) {
        float wo = Wo[d][c];
        #pragma unroll
        for (int kk = 0; kk < 16; ++kk) accv[kk] += wo * Wl[c][ks0 + kk];
    }
    #pragma unroll
    for (int kk = 0; kk < 16; ++kk)
        wc[(size_t)d * HD + h * 64 + ks0 + kk] = accv[kk];

    // v_src[h][k] = sum_c Wl[c][k] * asrc[h][c]; v_dst likewise
    if (t < 64) {
        float s = 0.f;
        for (int c = 0; c < 64; ++c) s += Wl[c][t] * __ldg(asrc + h * DIM + c);
        vv[h * DIM + t] = s;
    } else if (t < 128) {
        int k = t - 64;
        float s = 0.f;
        for (int c = 0; c < 64; ++c) s += Wl[c][k] * __ldg(adst + h * DIM + c);
        vv[(4 + h) * DIM + k] = s;
    }
}

// ---------------- scores: ssrc[i,h] = x[i] . v_src[h] (thread per node) ----------------
__global__ __launch_bounds__(256) void k_scores(
    const float* __restrict__ x, const float* __restrict__ vv,
    float* __restrict__ ssrc, float* __restrict__ sdst, int n)
{
    __shared__ float4 vs[8][16];
    int t = threadIdx.x;
    if (t < 128) {
        int v = t >> 4, k4 = t & 15;
        vs[v][k4] = *(const float4*)(vv + v * DIM + k4 * 4);
    }
    __syncthreads();
    int i = blockIdx.x * 256 + t;
    if (i >= n) return;
    const float4* xr = (const float4*)(x + (size_t)i * DIM);
    float acc[8] = {};
    #pragma unroll
    for (int k4 = 0; k4 < 16; ++k4) {
        float4 xv = xr[k4];
        #pragma unroll
        for (int v = 0; v < 8; ++v) {
            float4 w = vs[v][k4];
            acc[v] += xv.x * w.x + xv.y * w.y + xv.z * w.z + xv.w * w.w;
        }
    }
    *(float4*)(ssrc + (size_t)i * 4) = make_float4(acc[0], acc[1], acc[2], acc[3]);
    *(float4*)(sdst + (size_t)i * 4) = make_float4(acc[4], acc[5], acc[6], acc[7]);
}

// ---------------- scatter edges into dst-sorted order, alpha inline ----------------
__global__ void k_scatter(const int* __restrict__ ei,
                          const float* __restrict__ ssrc, const float* __restrict__ sdst,
                          int* __restrict__ cursor,
                          int* __restrict__ esrc, float* __restrict__ ealpha, int E)
{
    int e = blockIdx.x * blockDim.x + threadIdx.x;
    if (e >= E) return;
    int i = ei[e];        // dst
    int j = ei[E + e];    // src
    float4 sd = *(const float4*)(sdst + (size_t)i * 4);
    float4 ss = *(const float4*)(ssrc + (size_t)j * 4);
    float a0 = sd.x + ss.x; a0 = a0 > 0.f ? a0 : 0.2f * a0;
    float a1 = sd.y + ss.y; a1 = a1 > 0.f ? a1 : 0.2f * a1;
    float a2 = sd.z + ss.z; a2 = a2 > 0.f ? a2 : 0.2f * a2;
    float a3 = sd.w + ss.w; a3 = a3 > 0.f ? a3 : 0.2f * a3;
    int pos = atomicAdd(&cursor[i], 1);
    esrc[pos] = j;
    *(float4*)(ealpha + (size_t)pos * 4) =
        make_float4(expf(a0), expf(a1), expf(a2), expf(a3));
}

// ---------------- aggregation of raw x: one warp per dst node ----------------
// lane covers 2 floats of x[j]; 4 heads accumulated per lane.
__global__ __launch_bounds__(256) void k_agg_x(
    const int* __restrict__ off, const int* __restrict__ esrc,
    const float* __restrict__ ealpha, const float* __restrict__ x,
    float* __restrict__ agg, int n)
{
    int w    = (blockIdx.x * blockDim.x + threadIdx.x) >> 5;
    int lane = threadIdx.x & 31;
    if (w >= n) return;
    int beg = off[w], end = off[w + 1];
    float2 acc[4] = {};
    float  dsum[4] = {};

    int e = beg;
    int j = 0; float4 al = make_float4(0.f, 0.f, 0.f, 0.f);
    if (e < end) { j = esrc[e]; al = *(const float4*)(ealpha + (size_t)e * 4); }
    while (e < end) {
        int jn = 0; float4 aln = make_float4(0.f, 0.f, 0.f, 0.f);
        if (e + 1 < end) { jn = esrc[e + 1]; aln = *(const float4*)(ealpha + (size_t)(e + 1) * 4); }
        float2 xv = *(const float2*)(x + (size_t)j * DIM + lane * 2);
        acc[0].x += al.x * xv.x; acc[0].y += al.x * xv.y;
        acc[1].x += al.y * xv.x; acc[1].y += al.y * xv.y;
        acc[2].x += al.z * xv.x; acc[2].y += al.z * xv.y;
        acc[3].x += al.w * xv.x; acc[3].y += al.w * xv.y;
        dsum[0] += al.x; dsum[1] += al.y; dsum[2] += al.z; dsum[3] += al.w;
        j = jn; al = aln; ++e;
    }
    #pragma unroll
    for (int h = 0; h < 4; ++h) {
        float inv = 1.0f / (dsum[h] + 1e-9f);
        *(float2*)(agg + (size_t)w * HD + h * DIM + lane * 2) =
            make_float2(acc[h].x * inv, acc[h].y * inv);
    }
}

// ---------------- GEMM2 (tf32 mma, B hi/lo precomputed): out = LN(ELU(aggx@Wc^T+b)+x) ----------------
__global__ __launch_bounds__(256) void k_gemm2(
    const float* __restrict__ A,     // aggx [M,256]
    const float* __restrict__ B,     // Wc [64,256]
    const float* __restrict__ x,
    const float* __restrict__ bias,
    const float* __restrict__ lng, const float* __restrict__ lnb,
    float* __restrict__ out, int M)
{
    extern __shared__ float sm[];
    float*    As  = sm;                                  // [128][PAD]
    uint32_t* Bhi = (uint32_t*)(sm + AS_FLOATS);
    uint32_t* Blo = Bhi + BS_WORDS;
    const int t    = threadIdx.x;
    const int lane = t & 31;
    const int w    = t >> 5;
    const int gid  = lane >> 2;
    const int tid4 = lane & 3;
    const int m0   = blockIdx.x * 128;

    float acc[8][4] = {};
    const int r0 = w * 16 + gid;
    const int r1 = r0 + 8;

    for (int kc = 0; kc < HD; kc += 64) {
        #pragma unroll
        for (int it = 0; it < 8; ++it) {
            int idx = t + it * 256;
            int row = idx >> 4;
            int k4  = (idx & 15) * 4;
            float4 v = make_float4(0.f, 0.f, 0.f, 0.f);
            int gr = m0 + row;
            if (gr < M) v = *(const float4*)(A + (size_t)gr * HD + kc + k4);
            *(float4*)&As[row * PAD + k4] = v;
        }
        #pragma unroll
        for (int it = 0; it < 4; ++it) {
            int idx = t + it * 256;
            int nr  = idx >> 4;
            int k4  = (idx & 15) * 4;
            float4 v = *(const float4*)(B + (size_t)nr * HD + kc + k4);
            uint32_t hh, ll;
            hilo(v.x, hh, ll); Bhi[nr * PAD + k4 + 0] = hh; Blo[nr * PAD + k4 + 0] = ll;
            hilo(v.y, hh, ll); Bhi[nr * PAD + k4 + 1] = hh; Blo[nr * PAD + k4 + 1] = ll;
            hilo(v.z, hh, ll); Bhi[nr * PAD + k4 + 2] = hh; Blo[nr * PAD + k4 + 2] = ll;
            hilo(v.w, hh, ll); Bhi[nr * PAD + k4 + 3] = hh; Blo[nr * PAD + k4 + 3] = ll;
        }
        __syncthreads();

        #pragma unroll
        for (int ks = 0; ks < 8; ++ks) {
            int c0 = ks * 8 + tid4;
            int c1 = c0 + 4;
            uint32_t ah[4], al[4];
            hilo(As[r0 * PAD + c0], ah[0], al[0]);
            hilo(As[r1 * PAD + c0], ah[1], al[1]);
            hilo(As[r0 * PAD + c1], ah[2], al[2]);
            hilo(As[r1 * PAD + c1], ah[3], al[3]);
            #pragma unroll
            for (int nt = 0; nt < 8; ++nt) {
                int bi = (nt * 8 + gid) * PAD;
                uint32_t bh0 = Bhi[bi + c0], bl0 = Blo[bi + c0];
                uint32_t bh1 = Bhi[bi + c1], bl1 = Blo[bi + c1];
                mma_tf32(acc[nt][0], acc[nt][1], acc[nt][2], acc[nt][3],
                         ah[0], ah[1], ah[2], ah[3], bh0, bh1);
                mma_tf32(acc[nt][0], acc[nt][1], acc[nt][2], acc[nt][3],
                         ah[0], ah[1], ah[2], ah[3], bl0, bl1);
                mma_tf32(acc[nt][0], acc[nt][1], acc[nt][2], acc[nt][3],
                         al[0], al[1], al[2], al[3], bh0, bh1);
            }
        }
        __syncthreads();
    }

    // epilogue: bias + ELU + residual + LayerNorm; two rows per thread
    int gr0 = m0 + r0;
    int gr1 = m0 + r1;
    float y0[16], y1[16];
    float s0 = 0.f, q0 = 0.f, s1 = 0.f, q1 = 0.f;
    #pragma unroll
    for (int nt = 0; nt < 8; ++nt) {
        int col = nt * 8 + tid4 * 2;
        float2 bb = __ldg((const float2*)(bias + col));
        float2 x0 = (gr0 < M) ? *(const float2*)(x + (size_t)gr0 * DIM + col) : make_float2(0.f, 0.f);
        float2 x1 = (gr1 < M) ? *(const float2*)(x + (size_t)gr1 * DIM + col) : make_float2(0.f, 0.f);
        float v;
        v = acc[nt][0] + bb.x; v = v > 0.f ? v : (expf(v) - 1.f); y0[nt*2+0] = v + x0.x;
        v = acc[nt][1] + bb.y; v = v > 0.f ? v : (expf(v) - 1.f); y0[nt*2+1] = v + x0.y;
        v = acc[nt][2] + bb.x; v = v > 0.f ? v : (expf(v) - 1.f); y1[nt*2+0] = v + x1.x;
        v = acc[nt][3] + bb.y; v = v > 0.f ? v : (expf(v) - 1.f); y1[nt*2+1] = v + x1.y;
        s0 += y0[nt*2+0] + y0[nt*2+1]; q0 += y0[nt*2+0]*y0[nt*2+0] + y0[nt*2+1]*y0[nt*2+1];
        s1 += y1[nt*2+0] + y1[nt*2+1]; q1 += y1[nt*2+0]*y1[nt*2+0] + y1[nt*2+1]*y1[nt*2+1];
    }
    #pragma unroll
    for (int o = 1; o < 4; o <<= 1) {
        s0 += __shfl_xor_sync(0xffffffffu, s0, o);
        q0 += __shfl_xor_sync(0xffffffffu, q0, o);
        s1 += __shfl_xor_sync(0xffffffffu, s1, o);
        q1 += __shfl_xor_sync(0xffffffffu, q1, o);
    }
    float mu0  = s0 * (1.0f / 64.0f);
    float var0 = q0 * (1.0f / 64.0f) - mu0 * mu0;
    float inv0 = rsqrtf(var0 + 1e-5f);
    float mu1  = s1 * (1.0f / 64.0f);
    float var1 = q1 * (1.0f / 64.0f) - mu1 * mu1;
    float inv1 = rsqrtf(var1 + 1e-5f);
    #pragma unroll
    for (int nt = 0; nt < 8; ++nt) {
        int col = nt * 8 + tid4 * 2;
        float2 gg = __ldg((const float2*)(lng + col));
        float2 lb = __ldg((const float2*)(lnb + col));
        if (gr0 < M) {
            float2 o0;
            o0.x = (y0[nt*2+0] - mu0) * inv0 * gg.x + lb.x;
            o0.y = (y0[nt*2+1] - mu0) * inv0 * gg.y + lb.y;
            *(float2*)(out + (size_t)gr0 * DIM + col) = o0;
        }
        if (gr1 < M) {
            float2 o1;
            o1.x = (y1[nt*2+0] - mu1) * inv1 * gg.x + lb.x;
            o1.y = (y1[nt*2+1] - mu1) * inv1 * gg.y + lb.y;
            *(float2*)(out + (size_t)gr1 * DIM + col) = o1;
        }
    }
}

// ---------------- launch ----------------
extern "C" void kernel_launch(void* const* d_in, const int* in_sizes, int n_in,
                              void* d_out, int out_size)
{
    const float* x    = (const float*)d_in[0];
    const int*   ei   = (const int*)d_in[1];   // int32 [2,E]
    const float* Wlin = (const float*)d_in[2];
    const float* asrc = (const float*)d_in[3];
    const float* adst = (const float*)d_in[4];
    const float* Wout = (const float*)d_in[5];
    const float* bout = (const float*)d_in[6];
    const float* lng  = (const float*)d_in[7];
    const float* lnb  = (const float*)d_in[8];
    float*       out  = (float*)d_out;

    int n = in_sizes[0] / DIM;
    int E = in_sizes[1] / 2;
    if (n > NMAX) n = NMAX;
    if (E > EMAX) E = EMAX;

    float *p_agg, *p_ssrc, *p_sdst, *p_ealpha, *p_wc, *p_vv;
    int *p_cnt, *p_off, *p_cursor, *p_esrc;
    cudaGetSymbolAddress((void**)&p_agg,    g_agg);
    cudaGetSymbolAddress((void**)&p_ssrc,   g_ssrc);
    cudaGetSymbolAddress((void**)&p_sdst,   g_sdst);
    cudaGetSymbolAddress((void**)&p_cnt,    g_cnt);
    cudaGetSymbolAddress((void**)&p_off,    g_off);
    cudaGetSymbolAddress((void**)&p_cursor, g_cursor);
    cudaGetSymbolAddress((void**)&p_esrc,   g_esrc);
    cudaGetSymbolAddress((void**)&p_ealpha, g_ealpha);
    cudaGetSymbolAddress((void**)&p_wc,     g_wc);
    cudaGetSymbolAddress((void**)&p_vv,     g_vv);

    cudaFuncSetAttribute(k_gemm2, cudaFuncAttributeMaxDynamicSharedMemorySize, GEMM_SMEM_B);

    // 1) dst-degree histogram
    k_hzero<<<(n + 255) / 256, 256>>>(p_cnt, n);
    k_hist <<<(E + 255) / 256, 256>>>(ei, p_cnt, E);

    // 2) fold weights + score vectors (independent)
    k_prep<<<4, 256>>>(Wlin, Wout, asrc, adst, p_wc, p_vv);

    // 3) per-node scores from folded vectors
    k_scores<<<(n + 255) / 256, 256>>>(x, p_vv, p_ssrc, p_sdst, n);

    // 4) CSR offsets
    k_scan<<<1, 1024>>>(p_cnt, p_off, p_cursor, n);

    // 5) scatter edges (dst-sorted) with inline alpha
    k_scatter<<<(E + 255) / 256, 256>>>(ei, p_ssrc, p_sdst, p_cursor, p_esrc, p_ealpha, E);

    // 6) pull aggregation of raw x (4x less gather traffic than xh)
    k_agg_x<<<(n * 32 + 255) / 256, 256>>>(p_off, p_esrc, p_ealpha, x, p_agg, n);

    // 7) out = LN(ELU(aggx @ Wc^T + b) + x) (tf32 mma)
    k_gemm2<<<(n + 127) / 128, 256, GEMM_SMEM_B>>>(p_agg, p_wc, x, bout, lng, lnb, out, n);
}